// round 10
// baseline (speedup 1.0000x reference)
#include <cuda_runtime.h>
#include <cuda_bf16.h>
#include <cuda_fp16.h>
#include <cstdint>

// ---------------------------------------------------------------------------
// EntityClassify: 2-layer hetero R-GCN.
// R10: linearity restructure — aggregate RAW features (L2-resident arrays),
//      transform after: segsum(xW+b) = segsum(x)·W + deg·b.
//      GEMMs fuse the dual-relation ReLU combine in registers.
// ---------------------------------------------------------------------------

#define N_PAPER_MAX 200000
#define N_AUTHOR_MAX 100000
#define E_MAX 500000
#define NP_PAD 200064
#define NA_PAD 100064

// converted embeds (bf16)
__device__ uint16_t g_xpb[N_PAPER_MAX * 128];
__device__ uint16_t g_xab[N_AUTHOR_MAX * 128];
// layer-1 raw aggregates (bf16)
__device__ uint16_t g_aggC[N_PAPER_MAX * 128];   // sum xpb over cites
__device__ uint16_t g_aggW[N_PAPER_MAX * 128];   // sum xab over writes
__device__ uint16_t g_aggA[N_AUTHOR_MAX * 128];  // sum xpb over writtenby
// layer-1 outputs (fp16)
__device__ uint16_t g_h1p[N_PAPER_MAX * 128];
__device__ uint16_t g_h1a[N_AUTHOR_MAX * 128];
// layer-2 raw aggregates (fp16)
__device__ uint16_t g_a2C[N_PAPER_MAX * 128];    // sum h1p over cites
__device__ uint16_t g_a2W[N_PAPER_MAX * 128];    // sum h1a over writes
__device__ uint16_t g_a2A[N_AUTHOR_MAX * 128];   // sum h1p over writtenby

// CSR scratch (0=cites->paper, 1=writtenby->author, 2=writes->paper)
__device__ int g_offs0[NP_PAD + 1];
__device__ int g_offs1[NA_PAD + 1];
__device__ int g_offs2[NP_PAD + 1];
__device__ int g_csr0[E_MAX];
__device__ int g_csr1[E_MAX];
__device__ int g_csr2[E_MAX];
__device__ int g_deg[2 * NP_PAD + NA_PAD];
__device__ int g_cur[2 * NP_PAD + NA_PAD];
__device__ int g_bsum[3 * 64];

__device__ __forceinline__ uint32_t pack_bf2(float a, float b) {
    __nv_bfloat162 p = __floats2bfloat162_rn(a, b);
    return *reinterpret_cast<uint32_t*>(&p);
}
__device__ __forceinline__ uint32_t pack_h2(float a, float b) {
    __half2 p = __floats2half2_rn(a, b);
    return *reinterpret_cast<uint32_t*>(&p);
}
__device__ __forceinline__ void mma_bf16(float* c, const uint32_t* a,
                                         uint32_t b0, uint32_t b1) {
    asm volatile(
        "mma.sync.aligned.m16n8k16.row.col.f32.bf16.bf16.f32 "
        "{%0,%1,%2,%3}, {%4,%5,%6,%7}, {%8,%9}, {%0,%1,%2,%3};"
        : "+f"(c[0]), "+f"(c[1]), "+f"(c[2]), "+f"(c[3])
        : "r"(a[0]), "r"(a[1]), "r"(a[2]), "r"(a[3]), "r"(b0), "r"(b1));
}
__device__ __forceinline__ void mma_f16(float* c, const uint32_t* a,
                                        uint32_t b0, uint32_t b1) {
    asm volatile(
        "mma.sync.aligned.m16n8k16.row.col.f32.f16.f16.f32 "
        "{%0,%1,%2,%3}, {%4,%5,%6,%7}, {%8,%9}, {%0,%1,%2,%3};"
        : "+f"(c[0]), "+f"(c[1]), "+f"(c[2]), "+f"(c[3])
        : "r"(a[0]), "r"(a[1]), "r"(a[2]), "r"(a[3]), "r"(b0), "r"(b1));
}
__device__ __forceinline__ void bf2_acc(float4& acc, uint2 v) {
    float2 f0 = __bfloat1622float2(*reinterpret_cast<__nv_bfloat162*>(&v.x));
    float2 f1 = __bfloat1622float2(*reinterpret_cast<__nv_bfloat162*>(&v.y));
    acc.x += f0.x; acc.y += f0.y; acc.z += f1.x; acc.w += f1.y;
}
__device__ __forceinline__ void h2_acc(float4& acc, uint2 v) {
    float2 f0 = __half22float2(*reinterpret_cast<__half2*>(&v.x));
    float2 f1 = __half22float2(*reinterpret_cast<__half2*>(&v.y));
    acc.x += f0.x; acc.y += f0.y; acc.z += f1.x; acc.w += f1.y;
}

// ---------------------------------------------------------------------------
// Batched CSR build (unchanged)
// ---------------------------------------------------------------------------
__global__ void hist3(const int* __restrict__ d0, const int* __restrict__ d1,
                      const int* __restrict__ d2, int* __restrict__ deg,
                      int E0, int E1, int E2) {
    int i = blockIdx.x * blockDim.x + threadIdx.x;
    if (i < E0) {
        atomicAdd(&deg[d0[i]], 1);
    } else if (i < E0 + E1) {
        atomicAdd(&deg[NP_PAD + d1[i - E0]], 1);
    } else if (i < E0 + E1 + E2) {
        atomicAdd(&deg[NP_PAD + NA_PAD + d2[i - E0 - E1]], 1);
    }
}

__global__ void scan_block3(const int* __restrict__ deg,
                            int* __restrict__ offs0, int* __restrict__ offs1,
                            int* __restrict__ offs2, int* __restrict__ bsum,
                            int n0, int n1, int n2) {
    const int nb0 = (n0 + 4095) >> 12, nb1 = (n1 + 4095) >> 12;
    int b = blockIdx.x;
    int rel, lb, n;
    const int* dg;
    int* offs;
    if (b < nb0)            { rel = 0; lb = b;             dg = deg;                   offs = offs0; n = n0; }
    else if (b < nb0 + nb1) { rel = 1; lb = b - nb0;       dg = deg + NP_PAD;          offs = offs1; n = n1; }
    else                    { rel = 2; lb = b - nb0 - nb1; dg = deg + NP_PAD + NA_PAD; offs = offs2; n = n2; }

    const int i0 = lb * 4096 + threadIdx.x * 16;
    int vals[16];
    int s = 0;
#pragma unroll
    for (int j = 0; j < 16; j++) {
        int idx = i0 + j;
        int v = (idx < n) ? dg[idx] : 0;
        vals[j] = s;
        s += v;
    }
    int lane = threadIdx.x & 31, wid = threadIdx.x >> 5;
    int x = s;
#pragma unroll
    for (int o = 1; o < 32; o <<= 1) {
        int y = __shfl_up_sync(0xffffffffu, x, o);
        if (lane >= o) x += y;
    }
    __shared__ int wsum[8];
    if (lane == 31) wsum[wid] = x;
    __syncthreads();
    if (wid == 0 && lane < 8) {
        int y = wsum[lane];
#pragma unroll
        for (int o = 1; o < 8; o <<= 1) {
            int z = __shfl_up_sync(0xffu, y, o);
            if (lane >= o) y += z;
        }
        wsum[lane] = y;
    }
    __syncthreads();
    int thread_excl = (x - s) + (wid > 0 ? wsum[wid - 1] : 0);
#pragma unroll
    for (int j = 0; j < 16; j++) {
        int idx = i0 + j;
        if (idx < n) offs[idx] = thread_excl + vals[j];
    }
    if (threadIdx.x == 255) bsum[rel * 64 + lb] = thread_excl + s;
}

__global__ void scan_bsums3(int* __restrict__ bsum, int nb0, int nb1, int nb2) {
    int r = blockIdx.x;
    int nb = (r == 0) ? nb0 : (r == 1) ? nb1 : nb2;
    if (threadIdx.x == 0) {
        int* p = bsum + r * 64;
        int s = 0;
        for (int i = 0; i < nb; i++) { int x = p[i]; p[i] = s; s += x; }
    }
}

__global__ void scan_add3(int* __restrict__ offs0, int* __restrict__ offs1,
                          int* __restrict__ offs2, const int* __restrict__ bsum,
                          int* __restrict__ cur,
                          int n0, int n1, int n2, int E0, int E1, int E2) {
    int i = blockIdx.x * blockDim.x + threadIdx.x;
    if (i < n0) {
        int v = offs0[i] + bsum[i >> 12];
        offs0[i] = v; cur[i] = v;
        if (i == 0) offs0[n0] = E0;
    } else if (i < n0 + n1) {
        int j = i - n0;
        int v = offs1[j] + bsum[64 + (j >> 12)];
        offs1[j] = v; cur[NP_PAD + j] = v;
        if (j == 0) offs1[n1] = E1;
    } else if (i < n0 + n1 + n2) {
        int j = i - n0 - n1;
        int v = offs2[j] + bsum[128 + (j >> 12)];
        offs2[j] = v; cur[NP_PAD + NA_PAD + j] = v;
        if (j == 0) offs2[n2] = E2;
    }
}

__global__ void fill3(const int* __restrict__ s0, const int* __restrict__ d0,
                      const int* __restrict__ s1, const int* __restrict__ d1,
                      const int* __restrict__ s2, const int* __restrict__ d2,
                      int* __restrict__ cur,
                      int* __restrict__ c0, int* __restrict__ c1, int* __restrict__ c2,
                      int E0, int E1, int E2) {
    int i = blockIdx.x * blockDim.x + threadIdx.x;
    if (i < E0) {
        int p = atomicAdd(&cur[d0[i]], 1);
        c0[p] = s0[i];
    } else if (i < E0 + E1) {
        int j = i - E0;
        int p = atomicAdd(&cur[NP_PAD + d1[j]], 1);
        c1[p] = s1[j];
    } else if (i < E0 + E1 + E2) {
        int j = i - E0 - E1;
        int p = atomicAdd(&cur[NP_PAD + NA_PAD + d2[j]], 1);
        c2[p] = s2[j];
    }
}

// ---------------------------------------------------------------------------
// fp32 -> bf16 embed conversion (streamed)
// ---------------------------------------------------------------------------
__global__ void convert_bf16(const float* __restrict__ xp, const float* __restrict__ xa,
                             uint16_t* __restrict__ op, uint16_t* __restrict__ oa,
                             long np4, long na4) {
    long i = (long)blockIdx.x * blockDim.x + threadIdx.x;
    if (i < np4) {
        float4 v = __ldg(reinterpret_cast<const float4*>(xp) + i);
        uint2 o;
        o.x = pack_bf2(v.x, v.y);
        o.y = pack_bf2(v.z, v.w);
        reinterpret_cast<uint2*>(op)[i] = o;
    } else if (i < np4 + na4) {
        long j = i - np4;
        float4 v = __ldg(reinterpret_cast<const float4*>(xa) + j);
        uint2 o;
        o.x = pack_bf2(v.x, v.y);
        o.y = pack_bf2(v.z, v.w);
        reinterpret_cast<uint2*>(oa)[j] = o;
    }
}

// ---------------------------------------------------------------------------
// Raw-feature aggregation: warp per dst row, 3 relations in one launch.
// Rows 128-wide, 2 B/elem: lane reads uint2 (4 elems). 2-way unrolled.
// BF16=true: layer-1 (bf16 in/out). BF16=false: layer-2 (fp16 in/out).
// ---------------------------------------------------------------------------
template <bool BF16>
__global__ void agg3(const uint16_t* __restrict__ xp, const uint16_t* __restrict__ xa,
                     const int* __restrict__ offs0, const int* __restrict__ csr0,
                     const int* __restrict__ offs2, const int* __restrict__ csr2,
                     const int* __restrict__ offs1, const int* __restrict__ csr1,
                     uint16_t* __restrict__ aggC, uint16_t* __restrict__ aggW,
                     uint16_t* __restrict__ aggA, int nP, int nA) {
    int w = blockIdx.x * (blockDim.x >> 5) + (threadIdx.x >> 5);
    int lane = threadIdx.x & 31;
    const uint16_t* src;
    const int *offs, *csr;
    uint16_t* out;
    int d;
    if (w < nP)            { d = w;          src = xp; offs = offs0; csr = csr0; out = aggC; }
    else if (w < 2 * nP)   { d = w - nP;     src = xa; offs = offs2; csr = csr2; out = aggW; }
    else                   { d = w - 2 * nP; if (d >= nA) return;
                             src = xp; offs = offs1; csr = csr1; out = aggA; }

    float4 acc = make_float4(0.f, 0.f, 0.f, 0.f);
    int j = __ldg(offs + d), j1 = __ldg(offs + d + 1);
    for (; j + 2 <= j1; j += 2) {
        int sa = __ldg(csr + j), sb = __ldg(csr + j + 1);
        uint2 va = __ldg(reinterpret_cast<const uint2*>(src + (long)sa * 128) + lane);
        uint2 vb = __ldg(reinterpret_cast<const uint2*>(src + (long)sb * 128) + lane);
        if (BF16) { bf2_acc(acc, va); bf2_acc(acc, vb); }
        else      { h2_acc(acc, va);  h2_acc(acc, vb); }
    }
    if (j < j1) {
        int sa = __ldg(csr + j);
        uint2 va = __ldg(reinterpret_cast<const uint2*>(src + (long)sa * 128) + lane);
        if (BF16) bf2_acc(acc, va); else h2_acc(acc, va);
    }
    uint2 st;
    if (BF16) { st.x = pack_bf2(acc.x, acc.y); st.y = pack_bf2(acc.z, acc.w); }
    else      { st.x = pack_h2(acc.x, acc.y);  st.y = pack_h2(acc.z, acc.w); }
    reinterpret_cast<uint2*>(out + (long)d * 128)[lane] = st;
}

// ---------------------------------------------------------------------------
// Layer-1 GEMM with fused dual-relation combine:
//   paper: h1p = relu(relu(aggC@W1c + deg0*b1c) + aggW@W1wr + deg2*b1wr)
//   author: h1a = relu(aggA@W1wb + deg1*b1wb)
// bf16 MMA, in-register relu between phases. Inputs bf16, output fp16.
// ---------------------------------------------------------------------------
#define XS_STRIDE 68
#define GEMM128_SMEM (2 * 128 * XS_STRIDE * 4)

__global__ void __launch_bounds__(256)
gemm_l1(const uint16_t* __restrict__ aggC, const uint16_t* __restrict__ aggW,
        const uint16_t* __restrict__ aggA,
        const float* __restrict__ W1c,  const float* __restrict__ b1c,  const int* __restrict__ offs0,
        const float* __restrict__ W1wr, const float* __restrict__ b1wr, const int* __restrict__ offs2,
        const float* __restrict__ W1wb, const float* __restrict__ b1wb, const int* __restrict__ offs1,
        uint16_t* __restrict__ h1p, uint16_t* __restrict__ h1a,
        int nP, int nA, int nbP) {
    extern __shared__ uint32_t sm[];
    uint32_t* xs = sm;                    // 128 * 68
    uint32_t* wt = sm + 128 * XS_STRIDE;  // 128 * 68
    __shared__ float bs[128];

    const int tid = threadIdx.x;
    const int w = tid >> 5, lane = tid & 31;
    const int g = lane >> 2, tg = lane & 3;
    const int wrow = (w >> 1) * 32;
    const int wcol = (w & 1) * 64;

    const bool paper = (int)blockIdx.x < nbP;
    const int base = (paper ? blockIdx.x : blockIdx.x - nbP) * 128;
    const int M = paper ? nP : nA;
    const int nphase = paper ? 2 : 1;
    const uint16_t* Xl[2] = { paper ? aggC : aggA, aggW };
    const float* Wl[2]    = { paper ? W1c : W1wb,  W1wr };
    const float* bl[2]    = { paper ? b1c : b1wb,  b1wr };
    const int* ofl[2]     = { paper ? offs0 : offs1, offs2 };

    float acc[2][8][4];
#pragma unroll
    for (int mi = 0; mi < 2; mi++)
#pragma unroll
        for (int nt = 0; nt < 8; nt++)
#pragma unroll
            for (int j = 0; j < 4; j++) acc[mi][nt][j] = 0.f;

    for (int ph = 0; ph < nphase; ph++) {
        const uint16_t* X = Xl[ph];
        const float* W = Wl[ph];
        // X tile (bf16): 128 rows x 32 uint2
#pragma unroll
        for (int i = 0; i < 16; i++) {
            int idx = tid + 256 * i;
            int r = idx >> 5, c = idx & 31;
            int gr = base + r;
            uint2 v = make_uint2(0u, 0u);
            if (gr < M) v = __ldg(reinterpret_cast<const uint2*>(X + (long)gr * 128) + c);
            xs[r * XS_STRIDE + c * 2 + 0] = v.x;
            xs[r * XS_STRIDE + c * 2 + 1] = v.y;
        }
        // W (fp32) -> transposed bf16x2 smem
#pragma unroll
        for (int i = 0; i < 8; i++) {
            int u = tid + 256 * i;
            int n4 = u >> 6, kp = u & 63;
            float4 wa = __ldg(reinterpret_cast<const float4*>(W + (long)(2 * kp) * 128) + n4);
            float4 wb = __ldg(reinterpret_cast<const float4*>(W + (long)(2 * kp + 1) * 128) + n4);
            wt[(n4 * 4 + 0) * XS_STRIDE + kp] = pack_bf2(wa.x, wb.x);
            wt[(n4 * 4 + 1) * XS_STRIDE + kp] = pack_bf2(wa.y, wb.y);
            wt[(n4 * 4 + 2) * XS_STRIDE + kp] = pack_bf2(wa.z, wb.z);
            wt[(n4 * 4 + 3) * XS_STRIDE + kp] = pack_bf2(wa.w, wb.w);
        }
        if (tid < 128) bs[tid] = bl[ph][tid];
        __syncthreads();

#pragma unroll
        for (int s = 0; s < 8; s++) {
            uint32_t a[2][4];
#pragma unroll
            for (int mi = 0; mi < 2; mi++) {
                int rb = (wrow + mi * 16 + g) * XS_STRIDE + s * 8;
                int rb8 = rb + 8 * XS_STRIDE;
                a[mi][0] = xs[rb + tg];
                a[mi][1] = xs[rb8 + tg];
                a[mi][2] = xs[rb + 4 + tg];
                a[mi][3] = xs[rb8 + 4 + tg];
            }
#pragma unroll
            for (int nt = 0; nt < 8; nt++) {
                int cb = (wcol + nt * 8 + g) * XS_STRIDE + s * 8 + tg;
                uint32_t b0 = wt[cb];
                uint32_t b1 = wt[cb + 4];
                mma_bf16(acc[0][nt], a[0], b0, b1);
                mma_bf16(acc[1][nt], a[1], b0, b1);
            }
        }

        // per-row degrees for this phase's relation
        const int* offs = ofl[ph];
        float dg[2][2];
#pragma unroll
        for (int mi = 0; mi < 2; mi++) {
            int d0 = base + wrow + mi * 16 + g;
            int d1 = d0 + 8;
            dg[mi][0] = (d0 < M) ? (float)(__ldg(offs + d0 + 1) - __ldg(offs + d0)) : 0.f;
            dg[mi][1] = (d1 < M) ? (float)(__ldg(offs + d1 + 1) - __ldg(offs + d1)) : 0.f;
        }

        if (ph < nphase - 1) {
            // in-register: acc = relu(acc + deg * bias)
#pragma unroll
            for (int mi = 0; mi < 2; mi++)
#pragma unroll
                for (int nt = 0; nt < 8; nt++) {
                    int c = wcol + nt * 8 + tg * 2;
                    acc[mi][nt][0] = fmaxf(acc[mi][nt][0] + dg[mi][0] * bs[c], 0.f);
                    acc[mi][nt][1] = fmaxf(acc[mi][nt][1] + dg[mi][0] * bs[c + 1], 0.f);
                    acc[mi][nt][2] = fmaxf(acc[mi][nt][2] + dg[mi][1] * bs[c], 0.f);
                    acc[mi][nt][3] = fmaxf(acc[mi][nt][3] + dg[mi][1] * bs[c + 1], 0.f);
                }
            __syncthreads();   // bs/wt/xs reads done before next phase overwrites
        } else {
            uint16_t* out = paper ? h1p : h1a;
#pragma unroll
            for (int mi = 0; mi < 2; mi++) {
                int r0 = base + wrow + mi * 16 + g;
                int r1 = r0 + 8;
#pragma unroll
                for (int nt = 0; nt < 8; nt++) {
                    int c = wcol + nt * 8 + tg * 2;
                    if (r0 < M) {
                        float v0 = fmaxf(acc[mi][nt][0] + dg[mi][0] * bs[c], 0.f);
                        float v1 = fmaxf(acc[mi][nt][1] + dg[mi][0] * bs[c + 1], 0.f);
                        *reinterpret_cast<uint32_t*>(out + (long)r0 * 128 + c) = pack_h2(v0, v1);
                    }
                    if (r1 < M) {
                        float v2 = fmaxf(acc[mi][nt][2] + dg[mi][1] * bs[c], 0.f);
                        float v3 = fmaxf(acc[mi][nt][3] + dg[mi][1] * bs[c + 1], 0.f);
                        *reinterpret_cast<uint32_t*>(out + (long)r1 * 128 + c) = pack_h2(v2, v3);
                    }
                }
            }
        }
    }
}

// ---------------------------------------------------------------------------
// Layer-2 GEMM with fused dual-relation combine (N=16):
//   paper: out = relu(relu(a2C@W2c + deg0*b2c) + a2W@W2wr + deg2*b2wr)
//   author: out = relu(a2A@W2wb + deg1*b2wb)
// fp16 MMA; inputs fp16, output fp32 (d_out).
// ---------------------------------------------------------------------------
#define GEMM16_SMEM ((128 + 16) * XS_STRIDE * 4)

__global__ void __launch_bounds__(256)
gemm_l2(const uint16_t* __restrict__ a2C, const uint16_t* __restrict__ a2W,
        const uint16_t* __restrict__ a2A,
        const float* __restrict__ W2c,  const float* __restrict__ b2c,  const int* __restrict__ offs0,
        const float* __restrict__ W2wr, const float* __restrict__ b2wr, const int* __restrict__ offs2,
        const float* __restrict__ W2wb, const float* __restrict__ b2wb, const int* __restrict__ offs1,
        float* __restrict__ out_paper, float* __restrict__ out_author,
        int nP, int nA, int nbP) {
    extern __shared__ uint32_t sm[];
    uint32_t* xs = sm;                    // 128 * 68
    uint32_t* wt = sm + 128 * XS_STRIDE;  // 16 * 68
    __shared__ float bs[16];

    const int tid = threadIdx.x;
    const int w = tid >> 5, lane = tid & 31;
    const int g = lane >> 2, tg = lane & 3;
    const int wrow = (w >> 1) * 32;
    const int wcol = (w & 1) * 8;

    const bool paper = (int)blockIdx.x < nbP;
    const int base = (paper ? blockIdx.x : blockIdx.x - nbP) * 128;
    const int M = paper ? nP : nA;
    const int nphase = paper ? 2 : 1;
    const uint16_t* Xl[2] = { paper ? a2C : a2A, a2W };
    const float* Wl[2]    = { paper ? W2c : W2wb,  W2wr };
    const float* bl[2]    = { paper ? b2c : b2wb,  b2wr };
    const int* ofl[2]     = { paper ? offs0 : offs1, offs2 };

    float acc[2][4];
#pragma unroll
    for (int mi = 0; mi < 2; mi++)
#pragma unroll
        for (int j = 0; j < 4; j++) acc[mi][j] = 0.f;

    for (int ph = 0; ph < nphase; ph++) {
        const uint16_t* X = Xl[ph];
        const float* W = Wl[ph];
#pragma unroll
        for (int i = 0; i < 16; i++) {
            int idx = tid + 256 * i;
            int r = idx >> 5, c = idx & 31;
            int gr = base + r;
            uint2 v = make_uint2(0u, 0u);
            if (gr < M) v = __ldg(reinterpret_cast<const uint2*>(X + (long)gr * 128) + c);
            xs[r * XS_STRIDE + c * 2 + 0] = v.x;
            xs[r * XS_STRIDE + c * 2 + 1] = v.y;
        }
        // W [128,16] fp32 -> transposed fp16x2: wt[n][kp]
#pragma unroll
        for (int i = 0; i < 4; i++) {
            int u = tid + 256 * i;           // 0..1023
            int n = u >> 6, kp = u & 63;
            float a = __ldg(W + (long)(2 * kp) * 16 + n);
            float b = __ldg(W + (long)(2 * kp + 1) * 16 + n);
            wt[n * XS_STRIDE + kp] = pack_h2(a, b);
        }
        if (tid < 16) bs[tid] = bl[ph][tid];
        __syncthreads();

#pragma unroll
        for (int s = 0; s < 8; s++) {
            uint32_t a[2][4];
#pragma unroll
            for (int mi = 0; mi < 2; mi++) {
                int rb = (wrow + mi * 16 + g) * XS_STRIDE + s * 8;
                int rb8 = rb + 8 * XS_STRIDE;
                a[mi][0] = xs[rb + tg];
                a[mi][1] = xs[rb8 + tg];
                a[mi][2] = xs[rb + 4 + tg];
                a[mi][3] = xs[rb8 + 4 + tg];
            }
            int cb = (wcol + g) * XS_STRIDE + s * 8 + tg;
            uint32_t b0 = wt[cb];
            uint32_t b1 = wt[cb + 4];
            mma_f16(acc[0], a[0], b0, b1);
            mma_f16(acc[1], a[1], b0, b1);
        }

        const int* offs = ofl[ph];
        float dg[2][2];
#pragma unroll
        for (int mi = 0; mi < 2; mi++) {
            int d0 = base + wrow + mi * 16 + g;
            int d1 = d0 + 8;
            dg[mi][0] = (d0 < M) ? (float)(__ldg(offs + d0 + 1) - __ldg(offs + d0)) : 0.f;
            dg[mi][1] = (d1 < M) ? (float)(__ldg(offs + d1 + 1) - __ldg(offs + d1)) : 0.f;
        }
        int c = wcol + tg * 2;

        if (ph < nphase - 1) {
#pragma unroll
            for (int mi = 0; mi < 2; mi++) {
                acc[mi][0] = fmaxf(acc[mi][0] + dg[mi][0] * bs[c], 0.f);
                acc[mi][1] = fmaxf(acc[mi][1] + dg[mi][0] * bs[c + 1], 0.f);
                acc[mi][2] = fmaxf(acc[mi][2] + dg[mi][1] * bs[c], 0.f);
                acc[mi][3] = fmaxf(acc[mi][3] + dg[mi][1] * bs[c + 1], 0.f);
            }
            __syncthreads();
        } else {
            float* out = paper ? out_paper : out_author;
#pragma unroll
            for (int mi = 0; mi < 2; mi++) {
                int r0 = base + wrow + mi * 16 + g;
                int r1 = r0 + 8;
                if (r0 < M) {
                    float2 v = make_float2(fmaxf(acc[mi][0] + dg[mi][0] * bs[c], 0.f),
                                           fmaxf(acc[mi][1] + dg[mi][0] * bs[c + 1], 0.f));
                    *reinterpret_cast<float2*>(out + (long)r0 * 16 + c) = v;
                }
                if (r1 < M) {
                    float2 v = make_float2(fmaxf(acc[mi][2] + dg[mi][1] * bs[c], 0.f),
                                           fmaxf(acc[mi][3] + dg[mi][1] * bs[c + 1], 0.f));
                    *reinterpret_cast<float2*>(out + (long)r1 * 16 + c) = v;
                }
            }
        }
    }
}

static inline int cdiv(long a, long b) { return (int)((a + b - 1) / b); }

// ---------------------------------------------------------------------------
extern "C" void kernel_launch(void* const* d_in, const int* in_sizes, int n_in,
                              void* d_out, int out_size) {
    const float* embed_paper  = (const float*)d_in[0];
    const float* embed_author = (const float*)d_in[1];
    const float* W1_cites     = (const float*)d_in[2];
    const float* b1_cites     = (const float*)d_in[3];
    const float* W1_writtenby = (const float*)d_in[4];
    const float* b1_writtenby = (const float*)d_in[5];
    const float* W1_writes    = (const float*)d_in[6];
    const float* b1_writes    = (const float*)d_in[7];
    const float* W2_cites     = (const float*)d_in[8];
    const float* b2_cites     = (const float*)d_in[9];
    const float* W2_writtenby = (const float*)d_in[10];
    const float* b2_writtenby = (const float*)d_in[11];
    const float* W2_writes    = (const float*)d_in[12];
    const float* b2_writes    = (const float*)d_in[13];
    const int* cites_src      = (const int*)d_in[14];
    const int* cites_dst      = (const int*)d_in[15];
    const int* writtenby_src  = (const int*)d_in[16];
    const int* writtenby_dst  = (const int*)d_in[17];
    const int* writes_src     = (const int*)d_in[18];
    const int* writes_dst     = (const int*)d_in[19];

    const int n_paper  = in_sizes[0] / 128;
    const int n_author = in_sizes[1] / 128;
    const int E0 = in_sizes[14];
    const int E1 = in_sizes[16];
    const int E2 = in_sizes[18];

    uint16_t *xpb, *xab, *aggC, *aggW, *aggA, *h1p, *h1a, *a2C, *a2W, *a2A;
    cudaGetSymbolAddress((void**)&xpb,  g_xpb);
    cudaGetSymbolAddress((void**)&xab,  g_xab);
    cudaGetSymbolAddress((void**)&aggC, g_aggC);
    cudaGetSymbolAddress((void**)&aggW, g_aggW);
    cudaGetSymbolAddress((void**)&aggA, g_aggA);
    cudaGetSymbolAddress((void**)&h1p,  g_h1p);
    cudaGetSymbolAddress((void**)&h1a,  g_h1a);
    cudaGetSymbolAddress((void**)&a2C,  g_a2C);
    cudaGetSymbolAddress((void**)&a2W,  g_a2W);
    cudaGetSymbolAddress((void**)&a2A,  g_a2A);
    int *offs0, *offs1, *offs2, *csr0, *csr1, *csr2, *deg, *cur, *bsum;
    cudaGetSymbolAddress((void**)&offs0, g_offs0);
    cudaGetSymbolAddress((void**)&offs1, g_offs1);
    cudaGetSymbolAddress((void**)&offs2, g_offs2);
    cudaGetSymbolAddress((void**)&csr0, g_csr0);
    cudaGetSymbolAddress((void**)&csr1, g_csr1);
    cudaGetSymbolAddress((void**)&csr2, g_csr2);
    cudaGetSymbolAddress((void**)&deg,  g_deg);
    cudaGetSymbolAddress((void**)&cur,  g_cur);
    cudaGetSymbolAddress((void**)&bsum, g_bsum);

    cudaFuncSetAttribute(gemm_l1,
                         cudaFuncAttributeMaxDynamicSharedMemorySize, GEMM128_SMEM);
    cudaFuncSetAttribute(gemm_l2,
                         cudaFuncAttributeMaxDynamicSharedMemorySize, GEMM16_SMEM);

    // Side stream + events for CSR/convert overlap (created once; capture-safe).
    static cudaStream_t s_side = nullptr;
    static cudaEvent_t s_evFork = nullptr, s_evJoin = nullptr;
    if (!s_side) {
        cudaStreamCreateWithFlags(&s_side, cudaStreamNonBlocking);
        cudaEventCreateWithFlags(&s_evFork, cudaEventDisableTiming);
        cudaEventCreateWithFlags(&s_evJoin, cudaEventDisableTiming);
    }

    float* out_paper  = (float*)d_out;
    float* out_author = (float*)d_out + (long)n_paper * 16;

    // ---------------- Fork: CSR build on side stream ----------------
    cudaEventRecord(s_evFork, 0);
    cudaStreamWaitEvent(s_side, s_evFork, 0);

    cudaMemsetAsync(deg, 0, (size_t)(2 * NP_PAD + NA_PAD) * sizeof(int), s_side);
    hist3<<<cdiv((long)E0 + E1 + E2, 256), 256, 0, s_side>>>(
        cites_dst, writtenby_dst, writes_dst, deg, E0, E1, E2);
    int nb0 = cdiv(n_paper, 4096), nb1 = cdiv(n_author, 4096), nb2 = cdiv(n_paper, 4096);
    scan_block3<<<nb0 + nb1 + nb2, 256, 0, s_side>>>(deg, offs0, offs1, offs2, bsum,
                                                     n_paper, n_author, n_paper);
    scan_bsums3<<<3, 32, 0, s_side>>>(bsum, nb0, nb1, nb2);
    scan_add3<<<cdiv((long)n_paper + n_author + n_paper, 256), 256, 0, s_side>>>(
        offs0, offs1, offs2, bsum, cur, n_paper, n_author, n_paper, E0, E1, E2);
    fill3<<<cdiv((long)E0 + E1 + E2, 256), 256, 0, s_side>>>(
        cites_src, cites_dst, writtenby_src, writtenby_dst, writes_src, writes_dst,
        cur, csr0, csr1, csr2, E0, E1, E2);
    cudaEventRecord(s_evJoin, s_side);

    // ---------------- Main: embed conversion (independent of CSR) ----------
    const long np4 = (long)n_paper * 32, na4 = (long)n_author * 32;
    convert_bf16<<<cdiv(np4 + na4, 256), 256>>>(embed_paper, embed_author,
                                                xpb, xab, np4, na4);

    // ---------------- Join, then agg1 / gemm1 / agg2 / gemm2 ----------------
    cudaStreamWaitEvent(0, s_evJoin, 0);

    const int nbP = cdiv(n_paper, 128), nbA = cdiv(n_author, 128);

    agg3<true><<<cdiv((long)2 * n_paper + n_author, 8), 256>>>(
        xpb, xab, offs0, csr0, offs2, csr2, offs1, csr1,
        aggC, aggW, aggA, n_paper, n_author);

    gemm_l1<<<nbP + nbA, 256, GEMM128_SMEM>>>(
        aggC, aggW, aggA,
        W1_cites, b1_cites, offs0,
        W1_writes, b1_writes, offs2,
        W1_writtenby, b1_writtenby, offs1,
        h1p, h1a, n_paper, n_author, nbP);

    agg3<false><<<cdiv((long)2 * n_paper + n_author, 8), 256>>>(
        h1p, h1a, offs0, csr0, offs2, csr2, offs1, csr1,
        a2C, a2W, a2A, n_paper, n_author);

    gemm_l2<<<nbP + nbA, 256, GEMM16_SMEM>>>(
        a2C, a2W, a2A,
        W2_cites, b2_cites, offs0,
        W2_writes, b2_writes, offs2,
        W2_writtenby, b2_writtenby, offs1,
        out_paper, out_author, n_paper, n_author, nbP);
}

// round 11
// speedup vs baseline: 1.2714x; 1.2714x over previous
#include <cuda_runtime.h>
#include <cuda_bf16.h>
#include <cuda_fp16.h>
#include <cstdint>

// ---------------------------------------------------------------------------
// EntityClassify: 2-layer hetero R-GCN.
// R11: R9 structure (best) + __ldcs streaming X loads in gemm (keep messages
//      L2-resident) + 512-thread fused blocks (occupancy 62%->~100%).
// ---------------------------------------------------------------------------

#define N_PAPER_MAX 200000
#define N_AUTHOR_MAX 100000
#define E_MAX 500000
#define NP_PAD 200064
#define NA_PAD 100064

// layer-1 messages (bf16)
__device__ __nv_bfloat16 g_m0[N_PAPER_MAX * 128];   // embed_paper  @ W1_cites
__device__ __nv_bfloat16 g_m2[N_PAPER_MAX * 128];   // embed_paper  @ W1_writtenby
__device__ __nv_bfloat16 g_m1[N_AUTHOR_MAX * 128];  // embed_author @ W1_writes
// layer-2 messages (fp16)
__device__ __half g_mA[N_PAPER_MAX * 16];   // h1p @ W2_cites
__device__ __half g_mC[N_PAPER_MAX * 16];   // h1p @ W2_writtenby
__device__ __half g_mB[N_AUTHOR_MAX * 16];  // h1a @ W2_writes

// CSR scratch (0=cites->paper, 1=writtenby->author, 2=writes->paper)
__device__ int g_offs0[NP_PAD + 1];
__device__ int g_offs1[NA_PAD + 1];
__device__ int g_offs2[NP_PAD + 1];
__device__ int g_csr0[E_MAX];
__device__ int g_csr1[E_MAX];
__device__ int g_csr2[E_MAX];
__device__ int g_deg[2 * NP_PAD + NA_PAD];
__device__ int g_cur[2 * NP_PAD + NA_PAD];
__device__ int g_bsum[3 * 64];

__device__ __forceinline__ uint32_t pack_bf2(float a, float b) {
    __nv_bfloat162 p = __floats2bfloat162_rn(a, b);
    return *reinterpret_cast<uint32_t*>(&p);
}
__device__ __forceinline__ uint32_t pack_h2(float a, float b) {
    __half2 p = __floats2half2_rn(a, b);
    return *reinterpret_cast<uint32_t*>(&p);
}

__device__ __forceinline__ void mma_bf16(float* c, const uint32_t* a,
                                         uint32_t b0, uint32_t b1) {
    asm volatile(
        "mma.sync.aligned.m16n8k16.row.col.f32.bf16.bf16.f32 "
        "{%0,%1,%2,%3}, {%4,%5,%6,%7}, {%8,%9}, {%0,%1,%2,%3};"
        : "+f"(c[0]), "+f"(c[1]), "+f"(c[2]), "+f"(c[3])
        : "r"(a[0]), "r"(a[1]), "r"(a[2]), "r"(a[3]), "r"(b0), "r"(b1));
}

__device__ __forceinline__ void mma_f16(float* c, const uint32_t* a,
                                        uint32_t b0, uint32_t b1) {
    asm volatile(
        "mma.sync.aligned.m16n8k16.row.col.f32.f16.f16.f32 "
        "{%0,%1,%2,%3}, {%4,%5,%6,%7}, {%8,%9}, {%0,%1,%2,%3};"
        : "+f"(c[0]), "+f"(c[1]), "+f"(c[2]), "+f"(c[3])
        : "r"(a[0]), "r"(a[1]), "r"(a[2]), "r"(a[3]), "r"(b0), "r"(b1));
}

__device__ __forceinline__ void bf2_acc(float4& acc, uint2 v) {
    float2 f0 = __bfloat1622float2(*reinterpret_cast<__nv_bfloat162*>(&v.x));
    float2 f1 = __bfloat1622float2(*reinterpret_cast<__nv_bfloat162*>(&v.y));
    acc.x += f0.x; acc.y += f0.y; acc.z += f1.x; acc.w += f1.y;
}
__device__ __forceinline__ void h2_acc(float4& acc, uint2 v) {
    float2 f0 = __half22float2(*reinterpret_cast<__half2*>(&v.x));
    float2 f1 = __half22float2(*reinterpret_cast<__half2*>(&v.y));
    acc.x += f0.x; acc.y += f0.y; acc.z += f1.x; acc.w += f1.y;
}
__device__ __forceinline__ void relu4(float4& a) {
    a.x = fmaxf(a.x, 0.f); a.y = fmaxf(a.y, 0.f);
    a.z = fmaxf(a.z, 0.f); a.w = fmaxf(a.w, 0.f);
}

// ---------------------------------------------------------------------------
// Batched CSR build
// ---------------------------------------------------------------------------
__global__ void hist3(const int* __restrict__ d0, const int* __restrict__ d1,
                      const int* __restrict__ d2, int* __restrict__ deg,
                      int E0, int E1, int E2) {
    int i = blockIdx.x * blockDim.x + threadIdx.x;
    if (i < E0) {
        atomicAdd(&deg[d0[i]], 1);
    } else if (i < E0 + E1) {
        atomicAdd(&deg[NP_PAD + d1[i - E0]], 1);
    } else if (i < E0 + E1 + E2) {
        atomicAdd(&deg[NP_PAD + NA_PAD + d2[i - E0 - E1]], 1);
    }
}

__global__ void scan_block3(const int* __restrict__ deg,
                            int* __restrict__ offs0, int* __restrict__ offs1,
                            int* __restrict__ offs2, int* __restrict__ bsum,
                            int n0, int n1, int n2) {
    const int nb0 = (n0 + 4095) >> 12, nb1 = (n1 + 4095) >> 12;
    int b = blockIdx.x;
    int rel, lb, n;
    const int* dg;
    int* offs;
    if (b < nb0)            { rel = 0; lb = b;             dg = deg;                   offs = offs0; n = n0; }
    else if (b < nb0 + nb1) { rel = 1; lb = b - nb0;       dg = deg + NP_PAD;          offs = offs1; n = n1; }
    else                    { rel = 2; lb = b - nb0 - nb1; dg = deg + NP_PAD + NA_PAD; offs = offs2; n = n2; }

    const int i0 = lb * 4096 + threadIdx.x * 16;
    int vals[16];
    int s = 0;
#pragma unroll
    for (int j = 0; j < 16; j++) {
        int idx = i0 + j;
        int v = (idx < n) ? dg[idx] : 0;
        vals[j] = s;
        s += v;
    }
    int lane = threadIdx.x & 31, wid = threadIdx.x >> 5;
    int x = s;
#pragma unroll
    for (int o = 1; o < 32; o <<= 1) {
        int y = __shfl_up_sync(0xffffffffu, x, o);
        if (lane >= o) x += y;
    }
    __shared__ int wsum[8];
    if (lane == 31) wsum[wid] = x;
    __syncthreads();
    if (wid == 0 && lane < 8) {
        int y = wsum[lane];
#pragma unroll
        for (int o = 1; o < 8; o <<= 1) {
            int z = __shfl_up_sync(0xffu, y, o);
            if (lane >= o) y += z;
        }
        wsum[lane] = y;
    }
    __syncthreads();
    int thread_excl = (x - s) + (wid > 0 ? wsum[wid - 1] : 0);
#pragma unroll
    for (int j = 0; j < 16; j++) {
        int idx = i0 + j;
        if (idx < n) offs[idx] = thread_excl + vals[j];
    }
    if (threadIdx.x == 255) bsum[rel * 64 + lb] = thread_excl + s;
}

__global__ void scan_bsums3(int* __restrict__ bsum, int nb0, int nb1, int nb2) {
    int r = blockIdx.x;
    int nb = (r == 0) ? nb0 : (r == 1) ? nb1 : nb2;
    if (threadIdx.x == 0) {
        int* p = bsum + r * 64;
        int s = 0;
        for (int i = 0; i < nb; i++) { int x = p[i]; p[i] = s; s += x; }
    }
}

__global__ void scan_add3(int* __restrict__ offs0, int* __restrict__ offs1,
                          int* __restrict__ offs2, const int* __restrict__ bsum,
                          int* __restrict__ cur,
                          int n0, int n1, int n2, int E0, int E1, int E2) {
    int i = blockIdx.x * blockDim.x + threadIdx.x;
    if (i < n0) {
        int v = offs0[i] + bsum[i >> 12];
        offs0[i] = v; cur[i] = v;
        if (i == 0) offs0[n0] = E0;
    } else if (i < n0 + n1) {
        int j = i - n0;
        int v = offs1[j] + bsum[64 + (j >> 12)];
        offs1[j] = v; cur[NP_PAD + j] = v;
        if (j == 0) offs1[n1] = E1;
    } else if (i < n0 + n1 + n2) {
        int j = i - n0 - n1;
        int v = offs2[j] + bsum[128 + (j >> 12)];
        offs2[j] = v; cur[NP_PAD + NA_PAD + j] = v;
        if (j == 0) offs2[n2] = E2;
    }
}

__global__ void fill3(const int* __restrict__ s0, const int* __restrict__ d0,
                      const int* __restrict__ s1, const int* __restrict__ d1,
                      const int* __restrict__ s2, const int* __restrict__ d2,
                      int* __restrict__ cur,
                      int* __restrict__ c0, int* __restrict__ c1, int* __restrict__ c2,
                      int E0, int E1, int E2) {
    int i = blockIdx.x * blockDim.x + threadIdx.x;
    if (i < E0) {
        int p = atomicAdd(&cur[d0[i]], 1);
        c0[p] = s0[i];
    } else if (i < E0 + E1) {
        int j = i - E0;
        int p = atomicAdd(&cur[NP_PAD + d1[j]], 1);
        c1[p] = s1[j];
    } else if (i < E0 + E1 + E2) {
        int j = i - E0 - E1;
        int p = atomicAdd(&cur[NP_PAD + NA_PAD + d2[j]], 1);
        c2[p] = s2[j];
    }
}

// ---------------------------------------------------------------------------
// Layer-1 GEMM, multi-output (paper: 2 phases, author: 1), bf16 MMA.
// X loaded with __ldcs (read-once, evict-first) so message writes stay in L2.
// ---------------------------------------------------------------------------
#define XS_STRIDE 68
#define GEMM128_SMEM (2 * 128 * XS_STRIDE * 4)

__global__ void __launch_bounds__(256)
gemm128_l1(const float* __restrict__ Xp, const float* __restrict__ Xa,
           const float* __restrict__ Wc,  const float* __restrict__ bc,  __nv_bfloat16* __restrict__ m0,
           const float* __restrict__ Wwb, const float* __restrict__ bwb, __nv_bfloat16* __restrict__ m2,
           const float* __restrict__ Wwr, const float* __restrict__ bwr, __nv_bfloat16* __restrict__ m1,
           int nP, int nA, int nbP) {
    extern __shared__ uint32_t sm[];
    uint32_t* xs = sm;
    uint32_t* wt = sm + 128 * XS_STRIDE;
    __shared__ float bs[128];

    const int tid = threadIdx.x;
    const int wid = tid >> 5, lane = tid & 31;
    const int g = lane >> 2, tg = lane & 3;
    const int wrow = (wid >> 1) * 32;
    const int wcol = (wid & 1) * 64;

    const bool paper = (int)blockIdx.x < nbP;
    const float* X = paper ? Xp : Xa;
    const int M = paper ? nP : nA;
    const int row_base = (paper ? blockIdx.x : blockIdx.x - nbP) * 128;
    const int nphase = paper ? 2 : 1;
    const float* Wl[2]  = { paper ? Wc : Wwr,  Wwb };
    const float* bl[2]  = { paper ? bc : bwr,  bwb };
    __nv_bfloat16* Yl[2] = { paper ? m0 : m1,  m2 };

#pragma unroll
    for (int i = 0; i < 16; i++) {
        int idx = tid + 256 * i;
        int r = idx >> 5, c4 = idx & 31;
        int gr = row_base + r;
        float4 v = make_float4(0.f, 0.f, 0.f, 0.f);
        if (gr < M) v = __ldcs(reinterpret_cast<const float4*>(X + (long)gr * 128) + c4);
        xs[r * XS_STRIDE + c4 * 2 + 0] = pack_bf2(v.x, v.y);
        xs[r * XS_STRIDE + c4 * 2 + 1] = pack_bf2(v.z, v.w);
    }

    for (int ph = 0; ph < nphase; ph++) {
        const float* W = Wl[ph];
#pragma unroll
        for (int i = 0; i < 8; i++) {
            int u = tid + 256 * i;
            int n4 = u >> 6;
            int kp = u & 63;
            float4 wa = __ldg(reinterpret_cast<const float4*>(W + (long)(2 * kp) * 128) + n4);
            float4 wb = __ldg(reinterpret_cast<const float4*>(W + (long)(2 * kp + 1) * 128) + n4);
            wt[(n4 * 4 + 0) * XS_STRIDE + kp] = pack_bf2(wa.x, wb.x);
            wt[(n4 * 4 + 1) * XS_STRIDE + kp] = pack_bf2(wa.y, wb.y);
            wt[(n4 * 4 + 2) * XS_STRIDE + kp] = pack_bf2(wa.z, wb.z);
            wt[(n4 * 4 + 3) * XS_STRIDE + kp] = pack_bf2(wa.w, wb.w);
        }
        if (tid < 128) bs[tid] = bl[ph][tid];
        __syncthreads();

        float acc[2][8][4];
#pragma unroll
        for (int mi = 0; mi < 2; mi++)
#pragma unroll
            for (int nt = 0; nt < 8; nt++)
#pragma unroll
                for (int j = 0; j < 4; j++) acc[mi][nt][j] = 0.f;

#pragma unroll
        for (int s = 0; s < 8; s++) {
            uint32_t a[2][4];
#pragma unroll
            for (int mi = 0; mi < 2; mi++) {
                int rb = (wrow + mi * 16 + g) * XS_STRIDE + s * 8;
                int rb8 = rb + 8 * XS_STRIDE;
                a[mi][0] = xs[rb + tg];
                a[mi][1] = xs[rb8 + tg];
                a[mi][2] = xs[rb + 4 + tg];
                a[mi][3] = xs[rb8 + 4 + tg];
            }
#pragma unroll
            for (int nt = 0; nt < 8; nt++) {
                int cb = (wcol + nt * 8 + g) * XS_STRIDE + s * 8 + tg;
                uint32_t b0 = wt[cb];
                uint32_t b1 = wt[cb + 4];
                mma_bf16(acc[0][nt], a[0], b0, b1);
                mma_bf16(acc[1][nt], a[1], b0, b1);
            }
        }

        uint32_t* Yu = reinterpret_cast<uint32_t*>(Yl[ph]);
#pragma unroll
        for (int mi = 0; mi < 2; mi++) {
            int r0 = row_base + wrow + mi * 16 + g;
            int r1 = r0 + 8;
#pragma unroll
            for (int nt = 0; nt < 8; nt++) {
                int c = wcol + nt * 8 + tg * 2;
                if (r0 < M)
                    Yu[(long)r0 * 64 + (c >> 1)] = pack_bf2(acc[mi][nt][0] + bs[c], acc[mi][nt][1] + bs[c + 1]);
                if (r1 < M)
                    Yu[(long)r1 * 64 + (c >> 1)] = pack_bf2(acc[mi][nt][2] + bs[c], acc[mi][nt][3] + bs[c + 1]);
            }
        }
        __syncthreads();
    }
}

// ---------------------------------------------------------------------------
// 4-row interleaved gather (MLP=4). j/je per-row bounds, warp-uniform.
// ---------------------------------------------------------------------------
__device__ __forceinline__ void gather4_128(const __nv_bfloat16* __restrict__ m,
                                            const int* __restrict__ csr,
                                            int* j, const int* je, int lane, float4* acc) {
    while (true) {
        bool a0 = j[0] < je[0], a1 = j[1] < je[1];
        bool a2 = j[2] < je[2], a3 = j[3] < je[3];
        if (!(a0 | a1 | a2 | a3)) break;
        uint2 v0, v1, v2, v3;
        if (a0) { int s = __ldg(csr + j[0]); v0 = __ldg(reinterpret_cast<const uint2*>(m + (long)s * 128) + lane); }
        if (a1) { int s = __ldg(csr + j[1]); v1 = __ldg(reinterpret_cast<const uint2*>(m + (long)s * 128) + lane); }
        if (a2) { int s = __ldg(csr + j[2]); v2 = __ldg(reinterpret_cast<const uint2*>(m + (long)s * 128) + lane); }
        if (a3) { int s = __ldg(csr + j[3]); v3 = __ldg(reinterpret_cast<const uint2*>(m + (long)s * 128) + lane); }
        if (a0) { bf2_acc(acc[0], v0); j[0]++; }
        if (a1) { bf2_acc(acc[1], v1); j[1]++; }
        if (a2) { bf2_acc(acc[2], v2); j[2]++; }
        if (a3) { bf2_acc(acc[3], v3); j[3]++; }
    }
}

__device__ __forceinline__ void load_bounds4(const int* __restrict__ offs, int d0, int M,
                                             int* j, int* je) {
#pragma unroll
    for (int r = 0; r < 4; r++) {
        int d = d0 + r;
        if (d < M) { j[r] = __ldg(offs + d); je[r] = __ldg(offs + d + 1); }
        else { j[r] = 0; je[r] = 0; }
    }
}

// ---------------------------------------------------------------------------
// Fused gather_l1 + layer-2 transform. Block = 128 dst rows, 512 threads.
// Phase A: 16 warps x 8 rows (2 groups of 4 interleaved) -> h1 tile in smem.
// Phase B: h1_tile[128,128] @ W2cat[128,32] via fp16 MMA; 16 warps cover
//          8 row-groups x 2 col-groups (16 rows x 16 cols each).
// ---------------------------------------------------------------------------
#define FUSED_SMEM ((128 + 32) * XS_STRIDE * 4)

__global__ void __launch_bounds__(512)
fused_gather_l2(const __nv_bfloat16* __restrict__ m0, const int* __restrict__ offs0,
                const int* __restrict__ csr0,
                const __nv_bfloat16* __restrict__ m1, const int* __restrict__ offs2,
                const int* __restrict__ csr2,
                const __nv_bfloat16* __restrict__ m2, const int* __restrict__ offs1,
                const int* __restrict__ csr1,
                const float* __restrict__ Wc,  const float* __restrict__ bc,
                const float* __restrict__ Wwb, const float* __restrict__ bwb,
                const float* __restrict__ Wwr, const float* __restrict__ bwr,
                __half* __restrict__ mA, __half* __restrict__ mC, __half* __restrict__ mB,
                int nP, int nA, int nbP) {
    extern __shared__ uint32_t sm[];
    uint32_t* h1s = sm;                      // 128 * 68
    uint32_t* wt  = sm + 128 * XS_STRIDE;    // 32 * 68  (W2cat^T, fp16x2 along k)
    __shared__ float bsA[16], bsB[16];

    const int tid = threadIdx.x;
    const int w = tid >> 5, lane = tid & 31;
    const bool paper = (int)blockIdx.x < nbP;
    const int base = (paper ? blockIdx.x : blockIdx.x - nbP) * 128;
    const int M = paper ? nP : nA;

    // --- W2cat -> smem (fp16, transposed)
    const float* Wp = paper ? Wc : Wwr;
#pragma unroll
    for (int i = 0; i < 2; i++) {
        int u = tid + 512 * i;               // 0..1023
        int n = u >> 6, kp = u & 63;
        float a = __ldg(Wp + (2 * kp) * 16 + n);
        float b = __ldg(Wp + (2 * kp + 1) * 16 + n);
        wt[n * XS_STRIDE + kp] = pack_h2(a, b);
        float a2 = 0.f, b2 = 0.f;
        if (paper) {
            a2 = __ldg(Wwb + (2 * kp) * 16 + n);
            b2 = __ldg(Wwb + (2 * kp + 1) * 16 + n);
        }
        wt[(16 + n) * XS_STRIDE + kp] = pack_h2(a2, b2);
    }
    if (tid < 16) {
        bsA[tid] = paper ? bc[tid] : bwr[tid];
        bsB[tid] = paper ? bwb[tid] : 0.f;
    }

    // --- Phase A: 2 groups of 4 interleaved rows per warp (8 rows/warp)
#pragma unroll 1
    for (int grp = 0; grp < 2; grp++) {
        int rbase = w * 8 + grp * 4;
        int d0 = base + rbase;
        float4 acc[4];
#pragma unroll
        for (int r = 0; r < 4; r++) acc[r] = make_float4(0.f, 0.f, 0.f, 0.f);
        int j[4], je[4];

        if (paper) {
            load_bounds4(offs0, d0, M, j, je);
            gather4_128(m0, csr0, j, je, lane, acc);
#pragma unroll
            for (int r = 0; r < 4; r++) relu4(acc[r]);
            load_bounds4(offs2, d0, M, j, je);
            gather4_128(m1, csr2, j, je, lane, acc);
        } else {
            load_bounds4(offs1, d0, M, j, je);
            gather4_128(m2, csr1, j, je, lane, acc);
        }
#pragma unroll
        for (int r = 0; r < 4; r++) {
            relu4(acc[r]);
            h1s[(rbase + r) * XS_STRIDE + lane * 2 + 0] = pack_h2(acc[r].x, acc[r].y);
            h1s[(rbase + r) * XS_STRIDE + lane * 2 + 1] = pack_h2(acc[r].z, acc[r].w);
        }
    }
    __syncthreads();

    // --- Phase B: [128,128] @ [128,32] fp16 MMA (16 warps: 8 row x 2 col grps)
    const int g = lane >> 2, tg = lane & 3;
    const int wrow = (w >> 1) * 16;
    const int wcol = (w & 1) * 16;
    if (!paper && wcol == 16) return;        // authors: no secondary matrix

    float acc2[2][4];
#pragma unroll
    for (int nt = 0; nt < 2; nt++)
#pragma unroll
        for (int j2 = 0; j2 < 4; j2++) acc2[nt][j2] = 0.f;

#pragma unroll
    for (int s = 0; s < 8; s++) {
        uint32_t a[4];
        int rb = (wrow + g) * XS_STRIDE + s * 8;
        int rb8 = rb + 8 * XS_STRIDE;
        a[0] = h1s[rb + tg];
        a[1] = h1s[rb8 + tg];
        a[2] = h1s[rb + 4 + tg];
        a[3] = h1s[rb8 + 4 + tg];
#pragma unroll
        for (int nt = 0; nt < 2; nt++) {
            int cb = (wcol + nt * 8 + g) * XS_STRIDE + s * 8 + tg;
            uint32_t b0 = wt[cb];
            uint32_t b1 = wt[cb + 4];
            mma_f16(acc2[nt], a, b0, b1);
        }
    }

    const bool secondary = (wcol == 16);
    __half* out = secondary ? mC : (paper ? mA : mB);
    int r0 = base + wrow + g;
    int r1 = r0 + 8;
#pragma unroll
    for (int nt = 0; nt < 2; nt++) {
        int c = wcol + nt * 8 + tg * 2;
        int cc = c & 15;
        float bias0 = secondary ? bsB[cc] : bsA[cc];
        float bias1 = secondary ? bsB[cc + 1] : bsA[cc + 1];
        if (r0 < M)
            *reinterpret_cast<uint32_t*>(out + (long)r0 * 16 + cc) =
                pack_h2(acc2[nt][0] + bias0, acc2[nt][1] + bias1);
        if (r1 < M)
            *reinterpret_cast<uint32_t*>(out + (long)r1 * 16 + cc) =
                pack_h2(acc2[nt][2] + bias0, acc2[nt][3] + bias1);
    }
}

// ---------------------------------------------------------------------------
// Layer-2 fused gather (fp16 messages, 2-way unrolled). 4 threads per dst row.
// ---------------------------------------------------------------------------
__device__ __forceinline__ void gather_rel_16h(const __half* __restrict__ m,
                                               const int* __restrict__ csr,
                                               int j0, int j1, int q, float4& acc) {
    int j = j0;
    for (; j + 2 <= j1; j += 2) {
        int sa = __ldg(csr + j), sb = __ldg(csr + j + 1);
        uint2 va = __ldg(reinterpret_cast<const uint2*>(m + (long)sa * 16) + q);
        uint2 vb = __ldg(reinterpret_cast<const uint2*>(m + (long)sb * 16) + q);
        h2_acc(acc, va);
        h2_acc(acc, vb);
    }
    if (j < j1) {
        int sa = __ldg(csr + j);
        uint2 va = __ldg(reinterpret_cast<const uint2*>(m + (long)sa * 16) + q);
        h2_acc(acc, va);
    }
}

__global__ void gather_l2(const __half* __restrict__ mA, const int* __restrict__ offs0,
                          const int* __restrict__ csr0,
                          const __half* __restrict__ mB, const int* __restrict__ offs2,
                          const int* __restrict__ csr2,
                          const __half* __restrict__ mC, const int* __restrict__ offs1,
                          const int* __restrict__ csr1,
                          float* __restrict__ out_paper, float* __restrict__ out_author,
                          int nP, int nA) {
    long idx = (long)blockIdx.x * blockDim.x + threadIdx.x;
    if (idx >= (long)(nP + nA) * 4) return;
    int dr = (int)(idx >> 2), q = (int)(idx & 3);
    float4 acc = make_float4(0.f, 0.f, 0.f, 0.f);
    float* outp;

    if (dr < nP) {
        int d = dr;
        gather_rel_16h(mA, csr0, __ldg(offs0 + d), __ldg(offs0 + d + 1), q, acc);
        relu4(acc);
        gather_rel_16h(mB, csr2, __ldg(offs2 + d), __ldg(offs2 + d + 1), q, acc);
        outp = out_paper + (long)d * 16;
    } else {
        int d = dr - nP;
        gather_rel_16h(mC, csr1, __ldg(offs1 + d), __ldg(offs1 + d + 1), q, acc);
        outp = out_author + (long)d * 16;
    }
    relu4(acc);
    reinterpret_cast<float4*>(outp)[q] = acc;
}

static inline int cdiv(long a, long b) { return (int)((a + b - 1) / b); }

// ---------------------------------------------------------------------------
extern "C" void kernel_launch(void* const* d_in, const int* in_sizes, int n_in,
                              void* d_out, int out_size) {
    const float* embed_paper  = (const float*)d_in[0];
    const float* embed_author = (const float*)d_in[1];
    const float* W1_cites     = (const float*)d_in[2];
    const float* b1_cites     = (const float*)d_in[3];
    const float* W1_writtenby = (const float*)d_in[4];
    const float* b1_writtenby = (const float*)d_in[5];
    const float* W1_writes    = (const float*)d_in[6];
    const float* b1_writes    = (const float*)d_in[7];
    const float* W2_cites     = (const float*)d_in[8];
    const float* b2_cites     = (const float*)d_in[9];
    const float* W2_writtenby = (const float*)d_in[10];
    const float* b2_writtenby = (const float*)d_in[11];
    const float* W2_writes    = (const float*)d_in[12];
    const float* b2_writes    = (const float*)d_in[13];
    const int* cites_src      = (const int*)d_in[14];
    const int* cites_dst      = (const int*)d_in[15];
    const int* writtenby_src  = (const int*)d_in[16];
    const int* writtenby_dst  = (const int*)d_in[17];
    const int* writes_src     = (const int*)d_in[18];
    const int* writes_dst     = (const int*)d_in[19];

    const int n_paper  = in_sizes[0] / 128;
    const int n_author = in_sizes[1] / 128;
    const int E0 = in_sizes[14];
    const int E1 = in_sizes[16];
    const int E2 = in_sizes[18];

    __nv_bfloat16 *m0, *m1, *m2;
    __half *mA, *mB, *mC;
    cudaGetSymbolAddress((void**)&m0,  g_m0);
    cudaGetSymbolAddress((void**)&m1,  g_m1);
    cudaGetSymbolAddress((void**)&m2,  g_m2);
    cudaGetSymbolAddress((void**)&mA,  g_mA);
    cudaGetSymbolAddress((void**)&mB,  g_mB);
    cudaGetSymbolAddress((void**)&mC,  g_mC);
    int *offs0, *offs1, *offs2, *csr0, *csr1, *csr2, *deg, *cur, *bsum;
    cudaGetSymbolAddress((void**)&offs0, g_offs0);
    cudaGetSymbolAddress((void**)&offs1, g_offs1);
    cudaGetSymbolAddress((void**)&offs2, g_offs2);
    cudaGetSymbolAddress((void**)&csr0, g_csr0);
    cudaGetSymbolAddress((void**)&csr1, g_csr1);
    cudaGetSymbolAddress((void**)&csr2, g_csr2);
    cudaGetSymbolAddress((void**)&deg,  g_deg);
    cudaGetSymbolAddress((void**)&cur,  g_cur);
    cudaGetSymbolAddress((void**)&bsum, g_bsum);

    cudaFuncSetAttribute(gemm128_l1,
                         cudaFuncAttributeMaxDynamicSharedMemorySize, GEMM128_SMEM);
    cudaFuncSetAttribute(fused_gather_l2,
                         cudaFuncAttributeMaxDynamicSharedMemorySize, FUSED_SMEM);

    // Side stream + events for CSR/GEMM overlap (created once; capture-safe).
    static cudaStream_t s_side = nullptr;
    static cudaEvent_t s_evFork = nullptr, s_evJoin = nullptr;
    if (!s_side) {
        cudaStreamCreateWithFlags(&s_side, cudaStreamNonBlocking);
        cudaEventCreateWithFlags(&s_evFork, cudaEventDisableTiming);
        cudaEventCreateWithFlags(&s_evJoin, cudaEventDisableTiming);
    }

    float* out_paper  = (float*)d_out;
    float* out_author = (float*)d_out + (long)n_paper * 16;

    // ---------------- Fork: CSR build on side stream ----------------
    cudaEventRecord(s_evFork, 0);
    cudaStreamWaitEvent(s_side, s_evFork, 0);

    cudaMemsetAsync(deg, 0, (size_t)(2 * NP_PAD + NA_PAD) * sizeof(int), s_side);
    hist3<<<cdiv((long)E0 + E1 + E2, 256), 256, 0, s_side>>>(
        cites_dst, writtenby_dst, writes_dst, deg, E0, E1, E2);
    int nb0 = cdiv(n_paper, 4096), nb1 = cdiv(n_author, 4096), nb2 = cdiv(n_paper, 4096);
    scan_block3<<<nb0 + nb1 + nb2, 256, 0, s_side>>>(deg, offs0, offs1, offs2, bsum,
                                                     n_paper, n_author, n_paper);
    scan_bsums3<<<3, 32, 0, s_side>>>(bsum, nb0, nb1, nb2);
    scan_add3<<<cdiv((long)n_paper + n_author + n_paper, 256), 256, 0, s_side>>>(
        offs0, offs1, offs2, bsum, cur, n_paper, n_author, n_paper, E0, E1, E2);
    fill3<<<cdiv((long)E0 + E1 + E2, 256), 256, 0, s_side>>>(
        cites_src, cites_dst, writtenby_src, writtenby_dst, writes_src, writes_dst,
        cur, csr0, csr1, csr2, E0, E1, E2);
    cudaEventRecord(s_evJoin, s_side);

    // ---------------- Main stream: Layer-1 GEMM ----------------
    const int nbP128 = cdiv(n_paper, 128), nbA128 = cdiv(n_author, 128);
    gemm128_l1<<<nbP128 + nbA128, 256, GEMM128_SMEM>>>(
        embed_paper, embed_author,
        W1_cites, b1_cites, m0,
        W1_writtenby, b1_writtenby, m2,
        W1_writes, b1_writes, m1,
        n_paper, n_author, nbP128);

    // ---------------- Join, then fused gather+L2, final gather ----------------
    cudaStreamWaitEvent(0, s_evJoin, 0);

    fused_gather_l2<<<nbP128 + nbA128, 512, FUSED_SMEM>>>(
        m0, offs0, csr0, m1, offs2, csr2, m2, offs1, csr1,
        W2_cites, b2_cites, W2_writtenby, b2_writtenby, W2_writes, b2_writes,
        mA, mC, mB, n_paper, n_author, nbP128);

    gather_l2<<<cdiv(((long)n_paper + n_author) * 4, 256), 256>>>(
        mA, offs0, csr0, mB, offs2, csr2, mC, offs1, csr1,
        out_paper, out_author, n_paper, n_author);
}

// round 12
// speedup vs baseline: 1.5086x; 1.1865x over previous
#include <cuda_runtime.h>
#include <cuda_bf16.h>
#include <cuda_fp16.h>
#include <cstdint>

// ---------------------------------------------------------------------------
// EntityClassify: 2-layer hetero R-GCN.
// R12: exact R9 structure (best known: 365us) + ONE change: __ldcs on gemm X
//      loads (read-once stream, evict-first -> keep messages L2-resident).
// ---------------------------------------------------------------------------

#define N_PAPER_MAX 200000
#define N_AUTHOR_MAX 100000
#define E_MAX 500000
#define NP_PAD 200064
#define NA_PAD 100064

// layer-1 messages (bf16)
__device__ __nv_bfloat16 g_m0[N_PAPER_MAX * 128];   // embed_paper  @ W1_cites
__device__ __nv_bfloat16 g_m2[N_PAPER_MAX * 128];   // embed_paper  @ W1_writtenby
__device__ __nv_bfloat16 g_m1[N_AUTHOR_MAX * 128];  // embed_author @ W1_writes
// layer-2 messages (fp16)
__device__ __half g_mA[N_PAPER_MAX * 16];   // h1p @ W2_cites
__device__ __half g_mC[N_PAPER_MAX * 16];   // h1p @ W2_writtenby
__device__ __half g_mB[N_AUTHOR_MAX * 16];  // h1a @ W2_writes

// CSR scratch (0=cites->paper, 1=writtenby->author, 2=writes->paper)
__device__ int g_offs0[NP_PAD + 1];
__device__ int g_offs1[NA_PAD + 1];
__device__ int g_offs2[NP_PAD + 1];
__device__ int g_csr0[E_MAX];
__device__ int g_csr1[E_MAX];
__device__ int g_csr2[E_MAX];
__device__ int g_deg[2 * NP_PAD + NA_PAD];
__device__ int g_cur[2 * NP_PAD + NA_PAD];
__device__ int g_bsum[3 * 64];

__device__ __forceinline__ uint32_t pack_bf2(float a, float b) {
    __nv_bfloat162 p = __floats2bfloat162_rn(a, b);
    return *reinterpret_cast<uint32_t*>(&p);
}
__device__ __forceinline__ uint32_t pack_h2(float a, float b) {
    __half2 p = __floats2half2_rn(a, b);
    return *reinterpret_cast<uint32_t*>(&p);
}

__device__ __forceinline__ void mma_bf16(float* c, const uint32_t* a,
                                         uint32_t b0, uint32_t b1) {
    asm volatile(
        "mma.sync.aligned.m16n8k16.row.col.f32.bf16.bf16.f32 "
        "{%0,%1,%2,%3}, {%4,%5,%6,%7}, {%8,%9}, {%0,%1,%2,%3};"
        : "+f"(c[0]), "+f"(c[1]), "+f"(c[2]), "+f"(c[3])
        : "r"(a[0]), "r"(a[1]), "r"(a[2]), "r"(a[3]), "r"(b0), "r"(b1));
}

__device__ __forceinline__ void mma_f16(float* c, const uint32_t* a,
                                        uint32_t b0, uint32_t b1) {
    asm volatile(
        "mma.sync.aligned.m16n8k16.row.col.f32.f16.f16.f32 "
        "{%0,%1,%2,%3}, {%4,%5,%6,%7}, {%8,%9}, {%0,%1,%2,%3};"
        : "+f"(c[0]), "+f"(c[1]), "+f"(c[2]), "+f"(c[3])
        : "r"(a[0]), "r"(a[1]), "r"(a[2]), "r"(a[3]), "r"(b0), "r"(b1));
}

__device__ __forceinline__ void bf2_acc(float4& acc, uint2 v) {
    float2 f0 = __bfloat1622float2(*reinterpret_cast<__nv_bfloat162*>(&v.x));
    float2 f1 = __bfloat1622float2(*reinterpret_cast<__nv_bfloat162*>(&v.y));
    acc.x += f0.x; acc.y += f0.y; acc.z += f1.x; acc.w += f1.y;
}
__device__ __forceinline__ void h2_acc(float4& acc, uint2 v) {
    float2 f0 = __half22float2(*reinterpret_cast<__half2*>(&v.x));
    float2 f1 = __half22float2(*reinterpret_cast<__half2*>(&v.y));
    acc.x += f0.x; acc.y += f0.y; acc.z += f1.x; acc.w += f1.y;
}
__device__ __forceinline__ void relu4(float4& a) {
    a.x = fmaxf(a.x, 0.f); a.y = fmaxf(a.y, 0.f);
    a.z = fmaxf(a.z, 0.f); a.w = fmaxf(a.w, 0.f);
}

// ---------------------------------------------------------------------------
// Batched CSR build
// ---------------------------------------------------------------------------
__global__ void hist3(const int* __restrict__ d0, const int* __restrict__ d1,
                      const int* __restrict__ d2, int* __restrict__ deg,
                      int E0, int E1, int E2) {
    int i = blockIdx.x * blockDim.x + threadIdx.x;
    if (i < E0) {
        atomicAdd(&deg[d0[i]], 1);
    } else if (i < E0 + E1) {
        atomicAdd(&deg[NP_PAD + d1[i - E0]], 1);
    } else if (i < E0 + E1 + E2) {
        atomicAdd(&deg[NP_PAD + NA_PAD + d2[i - E0 - E1]], 1);
    }
}

__global__ void scan_block3(const int* __restrict__ deg,
                            int* __restrict__ offs0, int* __restrict__ offs1,
                            int* __restrict__ offs2, int* __restrict__ bsum,
                            int n0, int n1, int n2) {
    const int nb0 = (n0 + 4095) >> 12, nb1 = (n1 + 4095) >> 12;
    int b = blockIdx.x;
    int rel, lb, n;
    const int* dg;
    int* offs;
    if (b < nb0)            { rel = 0; lb = b;             dg = deg;                   offs = offs0; n = n0; }
    else if (b < nb0 + nb1) { rel = 1; lb = b - nb0;       dg = deg + NP_PAD;          offs = offs1; n = n1; }
    else                    { rel = 2; lb = b - nb0 - nb1; dg = deg + NP_PAD + NA_PAD; offs = offs2; n = n2; }

    const int i0 = lb * 4096 + threadIdx.x * 16;
    int vals[16];
    int s = 0;
#pragma unroll
    for (int j = 0; j < 16; j++) {
        int idx = i0 + j;
        int v = (idx < n) ? dg[idx] : 0;
        vals[j] = s;
        s += v;
    }
    int lane = threadIdx.x & 31, wid = threadIdx.x >> 5;
    int x = s;
#pragma unroll
    for (int o = 1; o < 32; o <<= 1) {
        int y = __shfl_up_sync(0xffffffffu, x, o);
        if (lane >= o) x += y;
    }
    __shared__ int wsum[8];
    if (lane == 31) wsum[wid] = x;
    __syncthreads();
    if (wid == 0 && lane < 8) {
        int y = wsum[lane];
#pragma unroll
        for (int o = 1; o < 8; o <<= 1) {
            int z = __shfl_up_sync(0xffu, y, o);
            if (lane >= o) y += z;
        }
        wsum[lane] = y;
    }
    __syncthreads();
    int thread_excl = (x - s) + (wid > 0 ? wsum[wid - 1] : 0);
#pragma unroll
    for (int j = 0; j < 16; j++) {
        int idx = i0 + j;
        if (idx < n) offs[idx] = thread_excl + vals[j];
    }
    if (threadIdx.x == 255) bsum[rel * 64 + lb] = thread_excl + s;
}

__global__ void scan_bsums3(int* __restrict__ bsum, int nb0, int nb1, int nb2) {
    int r = blockIdx.x;
    int nb = (r == 0) ? nb0 : (r == 1) ? nb1 : nb2;
    if (threadIdx.x == 0) {
        int* p = bsum + r * 64;
        int s = 0;
        for (int i = 0; i < nb; i++) { int x = p[i]; p[i] = s; s += x; }
    }
}

__global__ void scan_add3(int* __restrict__ offs0, int* __restrict__ offs1,
                          int* __restrict__ offs2, const int* __restrict__ bsum,
                          int* __restrict__ cur,
                          int n0, int n1, int n2, int E0, int E1, int E2) {
    int i = blockIdx.x * blockDim.x + threadIdx.x;
    if (i < n0) {
        int v = offs0[i] + bsum[i >> 12];
        offs0[i] = v; cur[i] = v;
        if (i == 0) offs0[n0] = E0;
    } else if (i < n0 + n1) {
        int j = i - n0;
        int v = offs1[j] + bsum[64 + (j >> 12)];
        offs1[j] = v; cur[NP_PAD + j] = v;
        if (j == 0) offs1[n1] = E1;
    } else if (i < n0 + n1 + n2) {
        int j = i - n0 - n1;
        int v = offs2[j] + bsum[128 + (j >> 12)];
        offs2[j] = v; cur[NP_PAD + NA_PAD + j] = v;
        if (j == 0) offs2[n2] = E2;
    }
}

__global__ void fill3(const int* __restrict__ s0, const int* __restrict__ d0,
                      const int* __restrict__ s1, const int* __restrict__ d1,
                      const int* __restrict__ s2, const int* __restrict__ d2,
                      int* __restrict__ cur,
                      int* __restrict__ c0, int* __restrict__ c1, int* __restrict__ c2,
                      int E0, int E1, int E2) {
    int i = blockIdx.x * blockDim.x + threadIdx.x;
    if (i < E0) {
        int p = atomicAdd(&cur[d0[i]], 1);
        c0[p] = s0[i];
    } else if (i < E0 + E1) {
        int j = i - E0;
        int p = atomicAdd(&cur[NP_PAD + d1[j]], 1);
        c1[p] = s1[j];
    } else if (i < E0 + E1 + E2) {
        int j = i - E0 - E1;
        int p = atomicAdd(&cur[NP_PAD + NA_PAD + d2[j]], 1);
        c2[p] = s2[j];
    }
}

// ---------------------------------------------------------------------------
// Layer-1 GEMM, multi-output (paper: 2 phases, author: 1), bf16 MMA.
// R12: X loaded with __ldcs (read-once, evict-first).
// ---------------------------------------------------------------------------
#define XS_STRIDE 68
#define GEMM128_SMEM (2 * 128 * XS_STRIDE * 4)

__global__ void __launch_bounds__(256)
gemm128_l1(const float* __restrict__ Xp, const float* __restrict__ Xa,
           const float* __restrict__ Wc,  const float* __restrict__ bc,  __nv_bfloat16* __restrict__ m0,
           const float* __restrict__ Wwb, const float* __restrict__ bwb, __nv_bfloat16* __restrict__ m2,
           const float* __restrict__ Wwr, const float* __restrict__ bwr, __nv_bfloat16* __restrict__ m1,
           int nP, int nA, int nbP) {
    extern __shared__ uint32_t sm[];
    uint32_t* xs = sm;
    uint32_t* wt = sm + 128 * XS_STRIDE;
    __shared__ float bs[128];

    const int tid = threadIdx.x;
    const int wid = tid >> 5, lane = tid & 31;
    const int g = lane >> 2, tg = lane & 3;
    const int wrow = (wid >> 1) * 32;
    const int wcol = (wid & 1) * 64;

    const bool paper = (int)blockIdx.x < nbP;
    const float* X = paper ? Xp : Xa;
    const int M = paper ? nP : nA;
    const int row_base = (paper ? blockIdx.x : blockIdx.x - nbP) * 128;
    const int nphase = paper ? 2 : 1;
    const float* Wl[2]  = { paper ? Wc : Wwr,  Wwb };
    const float* bl[2]  = { paper ? bc : bwr,  bwb };
    __nv_bfloat16* Yl[2] = { paper ? m0 : m1,  m2 };

#pragma unroll
    for (int i = 0; i < 16; i++) {
        int idx = tid + 256 * i;
        int r = idx >> 5, c4 = idx & 31;
        int gr = row_base + r;
        float4 v = make_float4(0.f, 0.f, 0.f, 0.f);
        if (gr < M) v = __ldcs(reinterpret_cast<const float4*>(X + (long)gr * 128) + c4);
        xs[r * XS_STRIDE + c4 * 2 + 0] = pack_bf2(v.x, v.y);
        xs[r * XS_STRIDE + c4 * 2 + 1] = pack_bf2(v.z, v.w);
    }

    for (int ph = 0; ph < nphase; ph++) {
        const float* W = Wl[ph];
#pragma unroll
        for (int i = 0; i < 8; i++) {
            int u = tid + 256 * i;
            int n4 = u >> 6;
            int kp = u & 63;
            float4 wa = __ldg(reinterpret_cast<const float4*>(W + (long)(2 * kp) * 128) + n4);
            float4 wb = __ldg(reinterpret_cast<const float4*>(W + (long)(2 * kp + 1) * 128) + n4);
            wt[(n4 * 4 + 0) * XS_STRIDE + kp] = pack_bf2(wa.x, wb.x);
            wt[(n4 * 4 + 1) * XS_STRIDE + kp] = pack_bf2(wa.y, wb.y);
            wt[(n4 * 4 + 2) * XS_STRIDE + kp] = pack_bf2(wa.z, wb.z);
            wt[(n4 * 4 + 3) * XS_STRIDE + kp] = pack_bf2(wa.w, wb.w);
        }
        if (tid < 128) bs[tid] = bl[ph][tid];
        __syncthreads();

        float acc[2][8][4];
#pragma unroll
        for (int mi = 0; mi < 2; mi++)
#pragma unroll
            for (int nt = 0; nt < 8; nt++)
#pragma unroll
                for (int j = 0; j < 4; j++) acc[mi][nt][j] = 0.f;

#pragma unroll
        for (int s = 0; s < 8; s++) {
            uint32_t a[2][4];
#pragma unroll
            for (int mi = 0; mi < 2; mi++) {
                int rb = (wrow + mi * 16 + g) * XS_STRIDE + s * 8;
                int rb8 = rb + 8 * XS_STRIDE;
                a[mi][0] = xs[rb + tg];
                a[mi][1] = xs[rb8 + tg];
                a[mi][2] = xs[rb + 4 + tg];
                a[mi][3] = xs[rb8 + 4 + tg];
            }
#pragma unroll
            for (int nt = 0; nt < 8; nt++) {
                int cb = (wcol + nt * 8 + g) * XS_STRIDE + s * 8 + tg;
                uint32_t b0 = wt[cb];
                uint32_t b1 = wt[cb + 4];
                mma_bf16(acc[0][nt], a[0], b0, b1);
                mma_bf16(acc[1][nt], a[1], b0, b1);
            }
        }

        uint32_t* Yu = reinterpret_cast<uint32_t*>(Yl[ph]);
#pragma unroll
        for (int mi = 0; mi < 2; mi++) {
            int r0 = row_base + wrow + mi * 16 + g;
            int r1 = r0 + 8;
#pragma unroll
            for (int nt = 0; nt < 8; nt++) {
                int c = wcol + nt * 8 + tg * 2;
                if (r0 < M)
                    Yu[(long)r0 * 64 + (c >> 1)] = pack_bf2(acc[mi][nt][0] + bs[c], acc[mi][nt][1] + bs[c + 1]);
                if (r1 < M)
                    Yu[(long)r1 * 64 + (c >> 1)] = pack_bf2(acc[mi][nt][2] + bs[c], acc[mi][nt][3] + bs[c + 1]);
            }
        }
        __syncthreads();
    }
}

// ---------------------------------------------------------------------------
// 4-row interleaved gather (MLP=4). j/je per-row bounds, warp-uniform.
// ---------------------------------------------------------------------------
__device__ __forceinline__ void gather4_128(const __nv_bfloat16* __restrict__ m,
                                            const int* __restrict__ csr,
                                            int* j, const int* je, int lane, float4* acc) {
    while (true) {
        bool a0 = j[0] < je[0], a1 = j[1] < je[1];
        bool a2 = j[2] < je[2], a3 = j[3] < je[3];
        if (!(a0 | a1 | a2 | a3)) break;
        uint2 v0, v1, v2, v3;
        if (a0) { int s = __ldg(csr + j[0]); v0 = __ldg(reinterpret_cast<const uint2*>(m + (long)s * 128) + lane); }
        if (a1) { int s = __ldg(csr + j[1]); v1 = __ldg(reinterpret_cast<const uint2*>(m + (long)s * 128) + lane); }
        if (a2) { int s = __ldg(csr + j[2]); v2 = __ldg(reinterpret_cast<const uint2*>(m + (long)s * 128) + lane); }
        if (a3) { int s = __ldg(csr + j[3]); v3 = __ldg(reinterpret_cast<const uint2*>(m + (long)s * 128) + lane); }
        if (a0) { bf2_acc(acc[0], v0); j[0]++; }
        if (a1) { bf2_acc(acc[1], v1); j[1]++; }
        if (a2) { bf2_acc(acc[2], v2); j[2]++; }
        if (a3) { bf2_acc(acc[3], v3); j[3]++; }
    }
}

__device__ __forceinline__ void load_bounds4(const int* __restrict__ offs, int d0, int M,
                                             int* j, int* je) {
#pragma unroll
    for (int r = 0; r < 4; r++) {
        int d = d0 + r;
        if (d < M) { j[r] = __ldg(offs + d); je[r] = __ldg(offs + d + 1); }
        else { j[r] = 0; je[r] = 0; }
    }
}

// ---------------------------------------------------------------------------
// Fused gather_l1 + layer-2 transform. Block = 128 dst rows, 256 threads.
// Phase A: 8 warps x 16 rows (4 groups of 4 interleaved) -> h1 tile in smem.
// Phase B: h1_tile[128,128] @ W2cat[128,32] via fp16 MMA.
// ---------------------------------------------------------------------------
#define FUSED_SMEM ((128 + 32) * XS_STRIDE * 4)

__global__ void __launch_bounds__(256)
fused_gather_l2(const __nv_bfloat16* __restrict__ m0, const int* __restrict__ offs0,
                const int* __restrict__ csr0,
                const __nv_bfloat16* __restrict__ m1, const int* __restrict__ offs2,
                const int* __restrict__ csr2,
                const __nv_bfloat16* __restrict__ m2, const int* __restrict__ offs1,
                const int* __restrict__ csr1,
                const float* __restrict__ Wc,  const float* __restrict__ bc,
                const float* __restrict__ Wwb, const float* __restrict__ bwb,
                const float* __restrict__ Wwr, const float* __restrict__ bwr,
                __half* __restrict__ mA, __half* __restrict__ mC, __half* __restrict__ mB,
                int nP, int nA, int nbP) {
    extern __shared__ uint32_t sm[];
    uint32_t* h1s = sm;                      // 128 * 68
    uint32_t* wt  = sm + 128 * XS_STRIDE;    // 32 * 68  (W2cat^T, fp16x2 along k)
    __shared__ float bsA[16], bsB[16];

    const int tid = threadIdx.x;
    const int w = tid >> 5, lane = tid & 31;
    const bool paper = (int)blockIdx.x < nbP;
    const int base = (paper ? blockIdx.x : blockIdx.x - nbP) * 128;
    const int M = paper ? nP : nA;

    // --- W2cat -> smem (fp16, transposed)
    const float* Wp = paper ? Wc : Wwr;
#pragma unroll
    for (int i = 0; i < 4; i++) {
        int u = tid + 256 * i;               // 0..1023
        int n = u >> 6, kp = u & 63;
        float a = __ldg(Wp + (2 * kp) * 16 + n);
        float b = __ldg(Wp + (2 * kp + 1) * 16 + n);
        wt[n * XS_STRIDE + kp] = pack_h2(a, b);
        float a2 = 0.f, b2 = 0.f;
        if (paper) {
            a2 = __ldg(Wwb + (2 * kp) * 16 + n);
            b2 = __ldg(Wwb + (2 * kp + 1) * 16 + n);
        }
        wt[(16 + n) * XS_STRIDE + kp] = pack_h2(a2, b2);
    }
    if (tid < 16) {
        bsA[tid] = paper ? bc[tid] : bwr[tid];
        bsB[tid] = paper ? bwb[tid] : 0.f;
    }

    // --- Phase A: 4 groups of 4 interleaved rows per warp
#pragma unroll 1
    for (int grp = 0; grp < 4; grp++) {
        int rbase = w * 16 + grp * 4;
        int d0 = base + rbase;
        float4 acc[4];
#pragma unroll
        for (int r = 0; r < 4; r++) acc[r] = make_float4(0.f, 0.f, 0.f, 0.f);
        int j[4], je[4];

        if (paper) {
            load_bounds4(offs0, d0, M, j, je);
            gather4_128(m0, csr0, j, je, lane, acc);
#pragma unroll
            for (int r = 0; r < 4; r++) relu4(acc[r]);
            load_bounds4(offs2, d0, M, j, je);
            gather4_128(m1, csr2, j, je, lane, acc);
        } else {
            load_bounds4(offs1, d0, M, j, je);
            gather4_128(m2, csr1, j, je, lane, acc);
        }
#pragma unroll
        for (int r = 0; r < 4; r++) {
            relu4(acc[r]);
            h1s[(rbase + r) * XS_STRIDE + lane * 2 + 0] = pack_h2(acc[r].x, acc[r].y);
            h1s[(rbase + r) * XS_STRIDE + lane * 2 + 1] = pack_h2(acc[r].z, acc[r].w);
        }
    }
    __syncthreads();

    // --- Phase B: [128,128] @ [128,32] fp16 MMA
    const int g = lane >> 2, tg = lane & 3;
    const int wrow = (w >> 1) * 32;
    const int wcol = (w & 1) * 16;
    if (!paper && wcol == 16) return;

    float acc2[2][2][4];
#pragma unroll
    for (int mi = 0; mi < 2; mi++)
#pragma unroll
        for (int nt = 0; nt < 2; nt++)
#pragma unroll
            for (int j2 = 0; j2 < 4; j2++) acc2[mi][nt][j2] = 0.f;

#pragma unroll
    for (int s = 0; s < 8; s++) {
        uint32_t a[2][4];
#pragma unroll
        for (int mi = 0; mi < 2; mi++) {
            int rb = (wrow + mi * 16 + g) * XS_STRIDE + s * 8;
            int rb8 = rb + 8 * XS_STRIDE;
            a[mi][0] = h1s[rb + tg];
            a[mi][1] = h1s[rb8 + tg];
            a[mi][2] = h1s[rb + 4 + tg];
            a[mi][3] = h1s[rb8 + 4 + tg];
        }
#pragma unroll
        for (int nt = 0; nt < 2; nt++) {
            int cb = (wcol + nt * 8 + g) * XS_STRIDE + s * 8 + tg;
            uint32_t b0 = wt[cb];
            uint32_t b1 = wt[cb + 4];
            mma_f16(acc2[0][nt], a[0], b0, b1);
            mma_f16(acc2[1][nt], a[1], b0, b1);
        }
    }

    const bool secondary = (wcol == 16);
    __half* out = secondary ? mC : (paper ? mA : mB);
#pragma unroll
    for (int mi = 0; mi < 2; mi++) {
        int r0 = base + wrow + mi * 16 + g;
        int r1 = r0 + 8;
#pragma unroll
        for (int nt = 0; nt < 2; nt++) {
            int c = wcol + nt * 8 + tg * 2;
            int cc = c & 15;
            float bias0 = secondary ? bsB[cc] : bsA[cc];
            float bias1 = secondary ? bsB[cc + 1] : bsA[cc + 1];
            if (r0 < M)
                *reinterpret_cast<uint32_t*>(out + (long)r0 * 16 + cc) =
                    pack_h2(acc2[mi][nt][0] + bias0, acc2[mi][nt][1] + bias1);
            if (r1 < M)
                *reinterpret_cast<uint32_t*>(out + (long)r1 * 16 + cc) =
                    pack_h2(acc2[mi][nt][2] + bias0, acc2[mi][nt][3] + bias1);
        }
    }
}

// ---------------------------------------------------------------------------
// Layer-2 fused gather (fp16 messages, 2-way unrolled). 4 threads per dst row.
// ---------------------------------------------------------------------------
__device__ __forceinline__ void gather_rel_16h(const __half* __restrict__ m,
                                               const int* __restrict__ csr,
                                               int j0, int j1, int q, float4& acc) {
    int j = j0;
    for (; j + 2 <= j1; j += 2) {
        int sa = __ldg(csr + j), sb = __ldg(csr + j + 1);
        uint2 va = __ldg(reinterpret_cast<const uint2*>(m + (long)sa * 16) + q);
        uint2 vb = __ldg(reinterpret_cast<const uint2*>(m + (long)sb * 16) + q);
        h2_acc(acc, va);
        h2_acc(acc, vb);
    }
    if (j < j1) {
        int sa = __ldg(csr + j);
        uint2 va = __ldg(reinterpret_cast<const uint2*>(m + (long)sa * 16) + q);
        h2_acc(acc, va);
    }
}

__global__ void gather_l2(const __half* __restrict__ mA, const int* __restrict__ offs0,
                          const int* __restrict__ csr0,
                          const __half* __restrict__ mB, const int* __restrict__ offs2,
                          const int* __restrict__ csr2,
                          const __half* __restrict__ mC, const int* __restrict__ offs1,
                          const int* __restrict__ csr1,
                          float* __restrict__ out_paper, float* __restrict__ out_author,
                          int nP, int nA) {
    long idx = (long)blockIdx.x * blockDim.x + threadIdx.x;
    if (idx >= (long)(nP + nA) * 4) return;
    int dr = (int)(idx >> 2), q = (int)(idx & 3);
    float4 acc = make_float4(0.f, 0.f, 0.f, 0.f);
    float* outp;

    if (dr < nP) {
        int d = dr;
        gather_rel_16h(mA, csr0, __ldg(offs0 + d), __ldg(offs0 + d + 1), q, acc);
        relu4(acc);
        gather_rel_16h(mB, csr2, __ldg(offs2 + d), __ldg(offs2 + d + 1), q, acc);
        outp = out_paper + (long)d * 16;
    } else {
        int d = dr - nP;
        gather_rel_16h(mC, csr1, __ldg(offs1 + d), __ldg(offs1 + d + 1), q, acc);
        outp = out_author + (long)d * 16;
    }
    relu4(acc);
    reinterpret_cast<float4*>(outp)[q] = acc;
}

static inline int cdiv(long a, long b) { return (int)((a + b - 1) / b); }

// ---------------------------------------------------------------------------
extern "C" void kernel_launch(void* const* d_in, const int* in_sizes, int n_in,
                              void* d_out, int out_size) {
    const float* embed_paper  = (const float*)d_in[0];
    const float* embed_author = (const float*)d_in[1];
    const float* W1_cites     = (const float*)d_in[2];
    const float* b1_cites     = (const float*)d_in[3];
    const float* W1_writtenby = (const float*)d_in[4];
    const float* b1_writtenby = (const float*)d_in[5];
    const float* W1_writes    = (const float*)d_in[6];
    const float* b1_writes    = (const float*)d_in[7];
    const float* W2_cites     = (const float*)d_in[8];
    const float* b2_cites     = (const float*)d_in[9];
    const float* W2_writtenby = (const float*)d_in[10];
    const float* b2_writtenby = (const float*)d_in[11];
    const float* W2_writes    = (const float*)d_in[12];
    const float* b2_writes    = (const float*)d_in[13];
    const int* cites_src      = (const int*)d_in[14];
    const int* cites_dst      = (const int*)d_in[15];
    const int* writtenby_src  = (const int*)d_in[16];
    const int* writtenby_dst  = (const int*)d_in[17];
    const int* writes_src     = (const int*)d_in[18];
    const int* writes_dst     = (const int*)d_in[19];

    const int n_paper  = in_sizes[0] / 128;
    const int n_author = in_sizes[1] / 128;
    const int E0 = in_sizes[14];
    const int E1 = in_sizes[16];
    const int E2 = in_sizes[18];

    __nv_bfloat16 *m0, *m1, *m2;
    __half *mA, *mB, *mC;
    cudaGetSymbolAddress((void**)&m0,  g_m0);
    cudaGetSymbolAddress((void**)&m1,  g_m1);
    cudaGetSymbolAddress((void**)&m2,  g_m2);
    cudaGetSymbolAddress((void**)&mA,  g_mA);
    cudaGetSymbolAddress((void**)&mB,  g_mB);
    cudaGetSymbolAddress((void**)&mC,  g_mC);
    int *offs0, *offs1, *offs2, *csr0, *csr1, *csr2, *deg, *cur, *bsum;
    cudaGetSymbolAddress((void**)&offs0, g_offs0);
    cudaGetSymbolAddress((void**)&offs1, g_offs1);
    cudaGetSymbolAddress((void**)&offs2, g_offs2);
    cudaGetSymbolAddress((void**)&csr0, g_csr0);
    cudaGetSymbolAddress((void**)&csr1, g_csr1);
    cudaGetSymbolAddress((void**)&csr2, g_csr2);
    cudaGetSymbolAddress((void**)&deg,  g_deg);
    cudaGetSymbolAddress((void**)&cur,  g_cur);
    cudaGetSymbolAddress((void**)&bsum, g_bsum);

    cudaFuncSetAttribute(gemm128_l1,
                         cudaFuncAttributeMaxDynamicSharedMemorySize, GEMM128_SMEM);
    cudaFuncSetAttribute(fused_gather_l2,
                         cudaFuncAttributeMaxDynamicSharedMemorySize, FUSED_SMEM);

    // Side stream + events for CSR/GEMM overlap (created once; capture-safe).
    static cudaStream_t s_side = nullptr;
    static cudaEvent_t s_evFork = nullptr, s_evJoin = nullptr;
    if (!s_side) {
        cudaStreamCreateWithFlags(&s_side, cudaStreamNonBlocking);
        cudaEventCreateWithFlags(&s_evFork, cudaEventDisableTiming);
        cudaEventCreateWithFlags(&s_evJoin, cudaEventDisableTiming);
    }

    float* out_paper  = (float*)d_out;
    float* out_author = (float*)d_out + (long)n_paper * 16;

    // ---------------- Fork: CSR build on side stream ----------------
    cudaEventRecord(s_evFork, 0);
    cudaStreamWaitEvent(s_side, s_evFork, 0);

    cudaMemsetAsync(deg, 0, (size_t)(2 * NP_PAD + NA_PAD) * sizeof(int), s_side);
    hist3<<<cdiv((long)E0 + E1 + E2, 256), 256, 0, s_side>>>(
        cites_dst, writtenby_dst, writes_dst, deg, E0, E1, E2);
    int nb0 = cdiv(n_paper, 4096), nb1 = cdiv(n_author, 4096), nb2 = cdiv(n_paper, 4096);
    scan_block3<<<nb0 + nb1 + nb2, 256, 0, s_side>>>(deg, offs0, offs1, offs2, bsum,
                                                     n_paper, n_author, n_paper);
    scan_bsums3<<<3, 32, 0, s_side>>>(bsum, nb0, nb1, nb2);
    scan_add3<<<cdiv((long)n_paper + n_author + n_paper, 256), 256, 0, s_side>>>(
        offs0, offs1, offs2, bsum, cur, n_paper, n_author, n_paper, E0, E1, E2);
    fill3<<<cdiv((long)E0 + E1 + E2, 256), 256, 0, s_side>>>(
        cites_src, cites_dst, writtenby_src, writtenby_dst, writes_src, writes_dst,
        cur, csr0, csr1, csr2, E0, E1, E2);
    cudaEventRecord(s_evJoin, s_side);

    // ---------------- Main stream: Layer-1 GEMM ----------------
    const int nbP128 = cdiv(n_paper, 128), nbA128 = cdiv(n_author, 128);
    gemm128_l1<<<nbP128 + nbA128, 256, GEMM128_SMEM>>>(
        embed_paper, embed_author,
        W1_cites, b1_cites, m0,
        W1_writtenby, b1_writtenby, m2,
        W1_writes, b1_writes, m1,
        n_paper, n_author, nbP128);

    // ---------------- Join, then fused gather+L2, final gather ----------------
    cudaStreamWaitEvent(0, s_evJoin, 0);

    fused_gather_l2<<<nbP128 + nbA128, 256, FUSED_SMEM>>>(
        m0, offs0, csr0, m1, offs2, csr2, m2, offs1, csr1,
        W2_cites, b2_cites, W2_writtenby, b2_writtenby, W2_writes, b2_writes,
        mA, mC, mB, n_paper, n_author, nbP128);

    gather_l2<<<cdiv(((long)n_paper + n_author) * 4, 256), 256>>>(
        mA, offs0, csr0, mB, offs2, csr2, mC, offs1, csr1,
        out_paper, out_author, n_paper, n_author);
}